// round 17
// baseline (speedup 1.0000x reference)
#include <cuda_runtime.h>
#include <cuda_bf16.h>
#include <cstdint>
#include <math.h>

// SpatialGRU 32x32, B=64,U=64,C=64.
// R16: R15 structure + ldmatrix fragment loads + split hi/lo h planes +
// diag-MMA hoisted before poll + mma-based k_pre.

#define TPB 256
#define LDA 200
#define LDW 200
#define LDUK 104
#define LDZ 65

__device__ float          g_x[1024 * 4096];
__device__ float          g_XZ[1024 * 28672];   // x@W+bias col-major [c448][r64]
__device__ float          g_xWij[1024 * 4096];  // [t][r][n]
__device__ __nv_bfloat16  g_Shi[1024 * 4096];   // h hi plane [t][r][n]
__device__ __nv_bfloat16  g_Slo[1024 * 4096];   // h lo plane
__device__ float          g_P[1024 * 2 * 4096]; // partials [row][n]
__device__ int            g_pz[1024];           // bits 0,1 = P ready
__device__ int            g_hdone[1024];        // bits 0,1 = h halves; full = 3

// r-CTA smem offsets
#define RWL 89600
#define RUH 128000
#define RUL 141312
#define RXZ 154624
#define RGH 179200
#define RGL 192512
#define RPS 205824
// z-CTA smem offsets
#define ZWL 102400
#define ZXZ 153600
#define ZXW 186368
#define ZZS 194560
#define SMEMSZ 227840

static __device__ __forceinline__ void mma16816(float* c, const uint32_t* a,
                                                const uint32_t* b) {
    asm volatile(
        "mma.sync.aligned.m16n8k16.row.col.f32.bf16.bf16.f32 "
        "{%0,%1,%2,%3}, {%4,%5,%6,%7}, {%8,%9}, {%0,%1,%2,%3};"
        : "+f"(c[0]), "+f"(c[1]), "+f"(c[2]), "+f"(c[3])
        : "r"(a[0]), "r"(a[1]), "r"(a[2]), "r"(a[3]), "r"(b[0]), "r"(b[1]));
}
static __device__ __forceinline__ void ldm4(uint32_t* r, uint32_t a) {
    asm volatile("ldmatrix.sync.aligned.m8n8.x4.shared.b16 {%0,%1,%2,%3}, [%4];"
        : "=r"(r[0]), "=r"(r[1]), "=r"(r[2]), "=r"(r[3]) : "r"(a));
}
static __device__ __forceinline__ int ld_acq(const int* p) {
    int v;
    asm volatile("ld.acquire.gpu.global.b32 %0, [%1];" : "=r"(v) : "l"(p) : "memory");
    return v;
}
static __device__ __forceinline__ void red_rel_or(int* p, int v) {
    asm volatile("red.release.gpu.global.or.b32 [%0], %1;" :: "l"(p), "r"(v) : "memory");
}
static __device__ __forceinline__ void bfsplit(float v, __nv_bfloat16* hi, __nv_bfloat16* lo) {
    __nv_bfloat16 h = __float2bfloat16(v);
    *hi = h;
    *lo = __float2bfloat16(v - __bfloat162float(h));
}
static __device__ __forceinline__ uint32_t sm32(const void* p) {
    return (uint32_t)__cvta_generic_to_shared(p);
}

// ---------------------------------------------------------------------------
__global__ void k_init() {
    int idx = blockIdx.x * blockDim.x + threadIdx.x;
    if (idx < 1024) { g_pz[idx] = 0; g_hdone[idx] = 0; }
}

__global__ void k_transpose(const float* __restrict__ in) {
    __shared__ float tile[32][33];
    int b = blockIdx.z, t0 = blockIdx.x * 32, c0 = blockIdx.y * 32;
    int tx = threadIdx.x, ty = threadIdx.y;
    tile[ty][tx] = in[b * 65536 + (c0 + ty) * 1024 + t0 + tx];
    __syncthreads();
    g_x[(t0 + ty) * 4096 + b * 64 + c0 + tx] = tile[tx][ty];
}

// ---------------------------------------------------------------------------
// k_pre (mma): per cell t, 128-col slice ct of [W-part 448 | Wij 64].
// XZ col-major + bias; xWij row-major + bias.
#define PLD 72
#define PXH 0
#define PXL 9216
#define PWH 18432
#define PWL 55296
#define PST 91648
#define PSMEM 124928
__global__ void __launch_bounds__(TPB)
k_pre(const float* __restrict__ W, const float* __restrict__ Wij,
      const float* __restrict__ bias) {
    extern __shared__ char psm[];
    __nv_bfloat16* xh = (__nv_bfloat16*)(psm + PXH);
    __nv_bfloat16* xl = (__nv_bfloat16*)(psm + PXL);
    __nv_bfloat16* wh = (__nv_bfloat16*)(psm + PWH);
    __nv_bfloat16* wl = (__nv_bfloat16*)(psm + PWL);
    float* stg = (float*)(psm + PST);
    int t = blockIdx.x, ct = blockIdx.y, tid = threadIdx.x;
    int w = tid >> 5, lane = tid & 31;
    int g = lane >> 2, q = lane & 3;

    for (int idx = tid; idx < 4096; idx += TPB) {
        int r = idx >> 6, k = idx & 63;
        bfsplit(g_x[t * 4096 + idx], &xh[r * PLD + k], &xl[r * PLD + k]);
    }
    for (int idx = tid; idx < 8192; idx += TPB) {
        int cl = idx & 127, k = idx >> 7;
        int gcol = ct * 128 + cl;
        float v = (gcol < 448) ? W[(192 + k) * 448 + gcol] : Wij[k * 64 + (gcol - 448)];
        bfsplit(v, &wh[cl * PLD + k], &wl[cl * PLD + k]);
    }
    __syncthreads();

    int rb = (w & 3) * 16, nb0 = (w >> 2) * 64;
    int arow = rb + (lane & 7) + ((lane & 8) ? 8 : 0);
    int akoff = (lane & 16) ? 8 : 0;
    uint32_t aH = sm32(xh) + (arow * PLD + akoff) * 2;
    uint32_t aL = sm32(xl) + (arow * PLD + akoff) * 2;
    int brow = (lane & 7) + ((lane & 16) ? 8 : 0);
    int bkoff = (lane & 8) ? 8 : 0;
    uint32_t bH[4], bL[4];
#pragma unroll
    for (int p = 0; p < 4; ++p) {
        int n0 = nb0 + p * 16;
        bH[p] = sm32(wh) + ((n0 + brow) * PLD + bkoff) * 2;
        bL[p] = sm32(wl) + ((n0 + brow) * PLD + bkoff) * 2;
    }

    float C[8][4];
#pragma unroll
    for (int a = 0; a < 8; ++a)
#pragma unroll
        for (int b = 0; b < 4; ++b) C[a][b] = 0.f;
#pragma unroll
    for (int kc = 0; kc < 4; ++kc) {
        int kb2 = kc * 32;
        uint32_t ah[4], al[4];
        ldm4(ah, aH + kb2); ldm4(al, aL + kb2);
#pragma unroll
        for (int p = 0; p < 4; ++p) {
            uint32_t bh[4], bl[4];
            ldm4(bh, bH[p] + kb2); ldm4(bl, bL[p] + kb2);
            mma16816(C[2 * p], ah, bh);     mma16816(C[2 * p], al, bh);
            mma16816(C[2 * p], ah, bl);
            mma16816(C[2 * p + 1], ah, bh + 2); mma16816(C[2 * p + 1], al, bh + 2);
            mma16816(C[2 * p + 1], ah, bl + 2);
        }
    }
#pragma unroll
    for (int nb = 0; nb < 8; ++nb)
#pragma unroll
        for (int e = 0; e < 4; ++e) {
            int row = rb + g + ((e & 2) ? 8 : 0);
            int cl = nb0 + nb * 8 + q * 2 + (e & 1);
            stg[cl * 65 + row] = C[nb][e];
        }
    __syncthreads();

    int nW = (ct < 3) ? 128 : 64;
    for (int idx = tid; idx < nW * 64; idx += TPB) {
        int cl = idx >> 6, r2 = idx & 63;
        int gcol = ct * 128 + cl;
        g_XZ[t * 28672 + gcol * 64 + r2] = stg[cl * 65 + r2] + __ldg(&bias[gcol]);
    }
    if (ct == 3)
        for (int idx = tid; idx < 4096; idx += TPB) {
            int n = idx & 63, r2 = idx >> 6;
            g_xWij[t * 4096 + r2 * 64 + n] = stg[(64 + n) * 65 + r2] + __ldg(&bias[448 + n]);
        }
}

// ---------------------------------------------------------------------------
__global__ void __launch_bounds__(TPB, 1)
k_scan(const float* __restrict__ W, const float* __restrict__ Urec,
       float* __restrict__ out) {
    extern __shared__ char sm[];
    __nv_bfloat16* Ah = (__nv_bfloat16*)(sm);
    __nv_bfloat16* Al = (__nv_bfloat16*)(sm + 25600);

    int tid = threadIdx.x, w = tid >> 5, lane = tid & 31;
    int g = lane >> 2, q = lane & 3;
    int gp = blockIdx.x >> 2, s = blockIdx.x & 3;
    bool isr = (s < 2);
    int zs = s - 2;
    int rb = (w & 3) * 16, cg = w >> 2;

    __nv_bfloat16* Wh = (__nv_bfloat16*)(sm + 51200);
    __nv_bfloat16* Wl = (__nv_bfloat16*)(sm + (isr ? RWL : ZWL));
    __nv_bfloat16* Uh = (__nv_bfloat16*)(sm + RUH);
    __nv_bfloat16* Ul = (__nv_bfloat16*)(sm + RUL);
    float* XZr = (float*)(sm + RXZ);
    __nv_bfloat16* Gh = (__nv_bfloat16*)(sm + RGH);
    __nv_bfloat16* Gl = (__nv_bfloat16*)(sm + RGL);
    float* PS  = (float*)(sm + RPS);
    float* XZz = (float*)(sm + ZXZ);
    float* xws = (float*)(sm + ZXW);
    float* Zs  = (float*)(sm + ZZS);

    // resident W slice
    int wcols = isr ? 96 : 128;
    for (int idx = tid; idx < wcols * 192; idx += TPB) {
        int cl = idx % wcols, k = idx / wcols;
        int gcol = isr ? (s * 96 + cl)
                       : (192 + (cl >> 5) * 64 + zs * 32 + (cl & 31));
        bfsplit(W[k * 448 + gcol], &Wh[cl * LDW + k], &Wl[cl * LDW + k]);
    }
    if (isr)
        for (int idx = tid; idx < 64 * 96; idx += TPB) {
            int n = idx & 63, k = idx >> 6;
            bfsplit(Urec[(s * 96 + k) * 64 + n], &Uh[n * LDUK + k], &Ul[n * LDUK + k]);
        }
    __syncthreads();

    // per-thread ldmatrix lane addresses
    int arowi = rb + (lane & 7) + ((lane & 8) ? 8 : 0);
    int akoff = (lane & 16) ? 8 : 0;
    uint32_t aOffH = sm32(Ah) + (arowi * LDA + akoff) * 2;
    uint32_t aOffL = sm32(Al) + (arowi * LDA + akoff) * 2;
    uint32_t gOffH = sm32(Gh) + (arowi * LDUK + akoff) * 2;
    uint32_t gOffL = sm32(Gl) + (arowi * LDUK + akoff) * 2;
    int browi = (lane & 7) + ((lane & 16) ? 8 : 0);
    int bkoff = (lane & 8) ? 8 : 0;
    int npair = isr ? 3 : 4;
    int nstep = isr ? 48 : 64;
    uint32_t wOffH[4], wOffL[4];
    for (int p = 0; p < npair; ++p) {
        int n0 = cg * nstep + p * 16;
        wOffH[p] = sm32(Wh) + ((n0 + browi) * LDW + bkoff) * 2;
        wOffL[p] = sm32(Wl) + ((n0 + browi) * LDW + bkoff) * 2;
    }
    uint32_t uOffH[2], uOffL[2];
    if (isr)
        for (int p = 0; p < 2; ++p) {
            int n0 = cg * 32 + p * 16;
            uOffH[p] = sm32(Uh) + ((n0 + browi) * LDUK + bkoff) * 2;
            uOffL[p] = sm32(Ul) + ((n0 + browi) * LDUK + bkoff) * 2;
        }

    for (int d = 0; d < 63; ++d) {
        int i0 = d > 31 ? d - 31 : 0;
        int nc = (d < 32) ? d + 1 : 63 - d;
        if (gp >= nc) continue;
        int i = i0 + gp, j = d - i, t = i * 32 + j;
        int tT = t - 32, tL = t - 1, tD = t - 33;
        bool hasT = (i > 0), hasL = (j > 0), hasD = (i > 0 && j > 0);

        // ---- prefetch (independent of neighbors) ----
        if (isr) {
            for (int idx = tid; idx < 96 * 64; idx += TPB) {
                int cl = idx >> 6, row = idx & 63;
                XZr[idx] = __ldg(&g_XZ[t * 28672 + (s * 96 + cl) * 64 + row]);
            }
        } else {
            for (int idx = tid; idx < 128 * 64; idx += TPB) {
                int cl = idx >> 6, row = idx & 63;
                int gcol = 192 + (cl >> 5) * 64 + zs * 32 + (cl & 31);
                XZz[idx] = __ldg(&g_XZ[t * 28672 + gcol * 64 + row]);
            }
            for (int idx = tid; idx < 2048; idx += TPB) {
                int row = idx >> 5, nn = idx & 31;
                xws[idx] = __ldg(&g_xWij[t * 4096 + row * 64 + zs * 32 + nn]);
            }
        }

        int NMB = isr ? 6 : 8;
        float C[8][4];
#pragma unroll
        for (int a = 0; a < 8; ++a)
#pragma unroll
            for (int b = 0; b < 4; ++b) C[a][b] = 0.f;

        // ---- diag part first (hD ready since d-2) ----
        if (tid == 0 && hasD) while (ld_acq(&g_hdone[tD]) != 3) {}
        __syncthreads();
#pragma unroll
        for (int it = 0; it < 4; ++it) {        // build A cols 128..191
            int idx = tid + it * TPB;
            int row = idx >> 4, q8 = idx & 15;
            int pl = q8 >> 3, col0 = (q8 & 7) * 8;
            uint4 v = hasD ? __ldcg((const uint4*)((pl ? (const void*)&g_Slo[tD * 4096 + row * 64 + col0]
                                                       : (const void*)&g_Shi[tD * 4096 + row * 64 + col0])))
                           : make_uint4(0, 0, 0, 0);
            __nv_bfloat16* dst = pl ? Al : Ah;
            *(uint4*)&dst[row * LDA + 128 + col0] = v;
        }
        __syncthreads();
#pragma unroll
        for (int kc = 8; kc < 12; ++kc) {
            int kb2 = kc * 32;
            uint32_t ah[4], al[4];
            ldm4(ah, aOffH + kb2); ldm4(al, aOffL + kb2);
            for (int p = 0; p < npair; ++p) {
                uint32_t bh[4], bl[4];
                ldm4(bh, wOffH[p] + kb2); ldm4(bl, wOffL[p] + kb2);
                mma16816(C[2 * p], ah, bh);         mma16816(C[2 * p], al, bh);
                mma16816(C[2 * p], ah, bl);
                mma16816(C[2 * p + 1], ah, bh + 2); mma16816(C[2 * p + 1], al, bh + 2);
                mma16816(C[2 * p + 1], ah, bl + 2);
            }
        }

        // ---- wait for top/left ----
        if (tid == 0 && hasT) while (ld_acq(&g_hdone[tT]) != 3) {}
        if (tid == 32 && hasL) while (ld_acq(&g_hdone[tL]) != 3) {}
        __syncthreads();
#pragma unroll
        for (int it = 0; it < 8; ++it) {        // build A cols 0..127 (top|left)
            int idx = tid + it * TPB;
            int blk = idx >> 10, rem = idx & 1023;
            int row = rem >> 4, q8 = rem & 15;
            int pl = q8 >> 3, col0 = (q8 & 7) * 8;
            int tsrc = blk ? tL : tT;
            bool has = blk ? hasL : hasT;
            uint4 v = has ? __ldcg((const uint4*)((pl ? (const void*)&g_Slo[tsrc * 4096 + row * 64 + col0]
                                                      : (const void*)&g_Shi[tsrc * 4096 + row * 64 + col0])))
                          : make_uint4(0, 0, 0, 0);
            __nv_bfloat16* dst = pl ? Al : Ah;
            *(uint4*)&dst[row * LDA + blk * 64 + col0] = v;
        }
        __syncthreads();
#pragma unroll
        for (int kc = 0; kc < 8; ++kc) {
            int kb2 = kc * 32;
            uint32_t ah[4], al[4];
            ldm4(ah, aOffH + kb2); ldm4(al, aOffL + kb2);
            for (int p = 0; p < npair; ++p) {
                uint32_t bh[4], bl[4];
                ldm4(bh, wOffH[p] + kb2); ldm4(bl, wOffL[p] + kb2);
                mma16816(C[2 * p], ah, bh);         mma16816(C[2 * p], al, bh);
                mma16816(C[2 * p], ah, bl);
                mma16816(C[2 * p + 1], ah, bh + 2); mma16816(C[2 * p + 1], al, bh + 2);
                mma16816(C[2 * p + 1], ah, bl + 2);
            }
        }

        if (isr) {
            // ===== r-CTA: G from frags -> P =====
#pragma unroll
            for (int nb = 0; nb < 6; ++nb)
#pragma unroll
                for (int e = 0; e < 4; ++e) {
                    int row = rb + g + ((e & 2) ? 8 : 0);
                    int cl = cg * 48 + nb * 8 + q * 2 + (e & 1);
                    float z = C[nb][e] + XZr[cl * 64 + row];
                    float sg = 1.f / (1.f + __expf(-z));
                    int rc = s * 96 + cl;
                    int ac = rc < 64 ? 64 + rc : (rc < 128 ? rc - 64 : rc);
                    float a = __bfloat162float(Ah[row * LDA + ac]) +
                              __bfloat162float(Al[row * LDA + ac]);
                    bfsplit(sg * a, &Gh[row * LDUK + cl], &Gl[row * LDUK + cl]);
                }
            __syncthreads();

            float P[4][4];
#pragma unroll
            for (int a = 0; a < 4; ++a)
#pragma unroll
                for (int b = 0; b < 4; ++b) P[a][b] = 0.f;
#pragma unroll
            for (int kc = 0; kc < 6; ++kc) {
                int kb2 = kc * 32;
                uint32_t ah[4], al[4];
                ldm4(ah, gOffH + kb2); ldm4(al, gOffL + kb2);
#pragma unroll
                for (int p = 0; p < 2; ++p) {
                    uint32_t bh[4], bl[4];
                    ldm4(bh, uOffH[p] + kb2); ldm4(bl, uOffL[p] + kb2);
                    mma16816(P[2 * p], ah, bh);         mma16816(P[2 * p], al, bh);
                    mma16816(P[2 * p], ah, bl);
                    mma16816(P[2 * p + 1], ah, bh + 2); mma16816(P[2 * p + 1], al, bh + 2);
                    mma16816(P[2 * p + 1], ah, bl + 2);
                }
            }
#pragma unroll
            for (int nb = 0; nb < 4; ++nb)
#pragma unroll
                for (int e = 0; e < 4; ++e) {
                    int row = rb + g + ((e & 2) ? 8 : 0);
                    int n = cg * 32 + nb * 8 + q * 2 + (e & 1);
                    PS[row * LDZ + n] = P[nb][e];
                }
            __syncthreads();
#pragma unroll
            for (int it = 0; it < 16; ++it) {
                int idx = tid + it * TPB;
                int r2 = idx >> 6, n2 = idx & 63;
                __stcg(&g_P[(t * 2 + s) * 4096 + idx], PS[r2 * LDZ + n2]);
            }
            __syncthreads();
            if (tid == 0) red_rel_or(&g_pz[t], 1 << s);
        } else {
            // ===== z-CTA: Z local -> epilogue =====
#pragma unroll
            for (int nb = 0; nb < 8; ++nb)
#pragma unroll
                for (int e = 0; e < 4; ++e) {
                    int row = rb + g + ((e & 2) ? 8 : 0);
                    int cl = cg * 64 + nb * 8 + q * 2 + (e & 1);
                    Zs[cl * LDZ + row] = C[nb][e];
                }
            if (tid == 0) while ((ld_acq(&g_pz[t]) & 3) != 3) {}
            __syncthreads();

            int np = tid & 31;
            int r0 = (tid >> 5) * 8;
            int n = zs * 32 + np;
#pragma unroll
            for (int e = 0; e < 8; ++e) {
                int row = r0 + e;
                float zi = Zs[np * LDZ + row]        + XZz[np * 64 + row];
                float zl = Zs[(32 + np) * LDZ + row] + XZz[(32 + np) * 64 + row];
                float zt = Zs[(64 + np) * LDZ + row] + XZz[(64 + np) * 64 + row];
                float zd = Zs[(96 + np) * LDZ + row] + XZz[(96 + np) * 64 + row];
                float m = fmaxf(fmaxf(zi, zl), fmaxf(zt, zd));
                float ei = __expf(zi - m), el = __expf(zl - m);
                float et = __expf(zt - m), ed = __expf(zd - m);
                float inv = 1.f / (ei + el + et + ed);
                float ht = __bfloat162float(Ah[row * LDA + n]) +
                           __bfloat162float(Al[row * LDA + n]);
                float hl = __bfloat162float(Ah[row * LDA + 64 + n]) +
                           __bfloat162float(Al[row * LDA + 64 + n]);
                float hd = __bfloat162float(Ah[row * LDA + 128 + n]) +
                           __bfloat162float(Al[row * LDA + 128 + n]);
                float p0 = __ldcg(&g_P[(t * 2 + 0) * 4096 + row * 64 + n]);
                float p1 = __ldcg(&g_P[(t * 2 + 1) * 4096 + row * 64 + n]);
                float pre = xws[row * 32 + np] + p0 + p1;
                pre = fminf(fmaxf(pre, -15.f), 15.f);
                float e2 = __expf(2.f * pre);
                float hh = (e2 - 1.f) / (e2 + 1.f);
                float h = (el * hl + et * ht + ed * hd + ei * hh) * inv;
                __nv_bfloat16 hhi = __float2bfloat16(h);
                __nv_bfloat16 hlo = __float2bfloat16(h - __bfloat162float(hhi));
                __stcg((unsigned short*)&g_Shi[t * 4096 + row * 64 + n],
                       (unsigned short)__bfloat16_as_ushort(hhi));
                __stcg((unsigned short*)&g_Slo[t * 4096 + row * 64 + n],
                       (unsigned short)__bfloat16_as_ushort(hlo));
                if (t == 1023) out[row * 64 + n] = h;
            }
            __syncthreads();
            if (tid == 0) red_rel_or(&g_hdone[t], 1 << zs);
        }
    }
}

// ---------------------------------------------------------------------------
extern "C" void kernel_launch(void* const* d_in, const int* in_sizes, int n_in,
                              void* d_out, int out_size) {
    const float* in   = (const float*)d_in[0];  // (64,64,32,32)
    const float* W    = (const float*)d_in[1];  // (256,448)
    const float* Urec = (const float*)d_in[2];  // (192,64)
    const float* bias = (const float*)d_in[3];  // (512)
    const float* Wij  = (const float*)d_in[4];  // (64,64)
    float* out = (float*)d_out;                 // (64,64)

    static int done = 0;
    if (!done) {
        cudaFuncSetAttribute(k_scan, cudaFuncAttributeMaxDynamicSharedMemorySize,
                             SMEMSZ);
        cudaFuncSetAttribute(k_pre, cudaFuncAttributeMaxDynamicSharedMemorySize,
                             PSMEM);
        done = 1;
    }
    k_init<<<4, 256>>>();
    k_transpose<<<dim3(32, 2, 64), dim3(32, 32)>>>(in);
    k_pre<<<dim3(1024, 4), TPB, PSMEM>>>(W, Wij, bias);
    k_scan<<<128, TPB, SMEMSZ>>>(W, Urec, out);
}